// round 16
// baseline (speedup 1.0000x reference)
#include <cuda_runtime.h>
#include <cuda_bf16.h>
#include <cstdint>

// GIB_Layer: M=50000 queries, K=32 support, 4 kinds x G=8 gaussian basis fns,
// masked mean over K, then (32 x 16) mixing matmul. REACH=1, EPS=1e-8.
//
// R14: two-kernel graph.
//   Kernel 1 (repack): points (N,3) AoS-12B -> static __device__ float4
//     scratch (16B/point). Coalesced, ~1 us.
//   Kernel 2 (main): R4/R12 structure (warp per query, grid-stride, QPW=8,
//     WPB=4, hoisted per-lane coefficients + 16-reg lambda slice with 1/K
//     folded in, ballot-compacted exp, pure-shuffle 32x16 epilogue) but the
//     scattered gather is now EXACTLY ONE aligned LDG.128 per lane: 32 lines
//     per query (the floor for 32 random points) instead of ~48, and no
//     extraction SEL chain.

#define GIB_K     32
#define GIB_OBS   16
#define GIB_F     32          // 4*G features
#define GIB_EPS   1e-8f
#define WPB       4           // warps per block
#define QPW       8           // target queries per warp
#define LOG2E     1.4426950408889634f
#define N_MAX     100000

__device__ float4 g_points4[N_MAX];     // 1.6 MB scratch (static, allowed)

__device__ __forceinline__ float fast_exp2(float x) {
    float y;
    asm("ex2.approx.ftz.f32 %0, %1;" : "=f"(y) : "f"(x));
    return y;
}

__global__ void repack_points_kernel(const float* __restrict__ points, int n)
{
    int i = blockIdx.x * blockDim.x + threadIdx.x;
    if (i < n) {
        // coalesced-ish 12B-stride reads, fully coalesced 16B writes
        g_points4[i] = make_float4(points[3 * i + 0],
                                   points[3 * i + 1],
                                   points[3 * i + 2], 0.f);
    }
}

__global__ __launch_bounds__(WPB * 32)
void gib_layer_kernel(const float* __restrict__ q_coords,
                      const int*   __restrict__ support_idxs,
                      const float* __restrict__ cy_radius,
                      const float* __restrict__ disk_radius,
                      const float* __restrict__ disk_width,
                      const float* __restrict__ cone_radius,
                      const float* __restrict__ cone_inc,
                      const float* __restrict__ ellip_radii,
                      const float* __restrict__ lambdas,
                      float* __restrict__ out,
                      int M)
{
    const int lane      = threadIdx.x & 31;
    const int warp_glb  = (blockIdx.x * WPB) + (threadIdx.x >> 5);
    const int num_warps = gridDim.x * WPB;

    // ---- per-lane weight coefficients (query-invariant):
    // lane -> (kind = lane>>3, g = lane&7); unified base-2 exponent
    //   a*x2 + b*y2 + c*z2 + d*rz + k0,  rz = sqrt(x2+y2+EPS)*z
    const int kind = lane >> 3;
    const int g    = lane & 7;
    float a, b, c, d, k0;
    {
        const float NHL = -0.5f * LOG2E;
        if (kind == 0) {                  // cylinder
            float r = cy_radius[g];
            float P = NHL / (r * r + GIB_EPS);
            a = P; b = P; c = 0.f; d = 0.f; k0 = 0.f;
        } else if (kind == 1) {           // cone
            float r   = cone_radius[g];
            float inc = cone_inc[g];
            float Q = NHL / (r * r + GIB_EPS);
            a = Q; b = Q; c = Q * inc * inc; d = -2.f * Q * inc; k0 = Q * GIB_EPS;
        } else if (kind == 2) {           // disk
            float dr = disk_radius[g], dw = disk_width[g];
            float Dr = NHL / (dr * dr + GIB_EPS);
            float Dw = NHL / (dw * dw + GIB_EPS);
            a = Dr; b = Dr; c = Dw; d = 0.f; k0 = 0.f;
        } else {                          // ellipsoid
            float ra = ellip_radii[g * 3 + 0];
            float rb = ellip_radii[g * 3 + 1];
            float rc = ellip_radii[g * 3 + 2];
            a = NHL / (ra * ra + GIB_EPS);
            b = NHL / (rb * rb + GIB_EPS);
            c = NHL / (rc * rc + GIB_EPS);
            d = 0.f; k0 = 0.f;
        }
    }

    // ---- per-lane lambda slice (query-invariant), 1/K folded in.
    // lane l handles output o=l&15 over features f=(l&16)+j, j=0..15.
    const int o_idx = lane & 15;
    const int f0    = lane & 16;
    float lam[16];
    #pragma unroll
    for (int j = 0; j < 16; j++)
        lam[j] = lambdas[(f0 + j) * GIB_OBS + o_idx] * (1.0f / (float)GIB_K);

    // ---- query loop (grid-stride): whole warp shares one m per iteration.
    for (int m = warp_glb; m < M; m += num_warps) {
        const int pi = support_idxs[m * GIB_K + lane];
        const float4 v = g_points4[pi];    // single aligned LDG.128

        const float qx = q_coords[3 * m + 0];
        const float qy = q_coords[3 * m + 1];
        const float qz = q_coords[3 * m + 2];

        const float x = v.x - qx;
        const float y = v.y - qy;
        const float z = v.z - qz;

        const float x2 = x * x, y2 = y * y, z2 = z * z;
        const float d2 = x2 + y2 + z2;
        const float rz = sqrtf(x2 + y2 + GIB_EPS) * z;

        unsigned bal = __ballot_sync(0xffffffffu, d2 <= 1.0f);   // REACH^2=1
        float acc = 0.f;
        while (bal) {
            const int j = __ffs(bal) - 1;
            bal &= bal - 1;
            const float bx2 = __shfl_sync(0xffffffffu, x2, j);
            const float by2 = __shfl_sync(0xffffffffu, y2, j);
            const float bz2 = __shfl_sync(0xffffffffu, z2, j);
            const float brz = __shfl_sync(0xffffffffu, rz, j);
            const float arg = fmaf(a, bx2, fmaf(b, by2, fmaf(c, bz2, fmaf(d, brz, k0))));
            acc += fast_exp2(arg);
        }
        // 1/K folded into lam

        // ---- epilogue: out[m, o] = sum_f feat[f] * lambdas[f, o].
        float oacc = 0.f;
        #pragma unroll
        for (int j = 0; j < 16; j++) {
            const float bf = __shfl_sync(0xffffffffu, acc, f0 | j);
            oacc = fmaf(bf, lam[j], oacc);
        }
        oacc += __shfl_xor_sync(0xffffffffu, oacc, 16);

        if (lane < GIB_OBS)
            out[m * GIB_OBS + lane] = oacc;
    }
}

extern "C" void kernel_launch(void* const* d_in, const int* in_sizes, int n_in,
                              void* d_out, int out_size)
{
    const float* points       = (const float*)d_in[0];
    const float* q_coords     = (const float*)d_in[1];
    const int*   support_idxs = (const int*)  d_in[2];
    const float* cy_radius    = (const float*)d_in[3];
    const float* disk_radius  = (const float*)d_in[4];
    const float* disk_width   = (const float*)d_in[5];
    const float* cone_radius  = (const float*)d_in[6];
    const float* cone_inc     = (const float*)d_in[7];
    const float* ellip_radii  = (const float*)d_in[8];
    const float* lambdas      = (const float*)d_in[9];
    float* out = (float*)d_out;

    int n = in_sizes[0] / 3;              // points is (N, 3)
    if (n > N_MAX) n = N_MAX;
    const int M = in_sizes[1] / 3;        // q_coords is (M, 3)

    repack_points_kernel<<<(n + 255) / 256, 256>>>(points, n);

    int blocks = (M + (WPB * QPW) - 1) / (WPB * QPW);
    if (blocks < 1) blocks = 1;
    gib_layer_kernel<<<blocks, WPB * 32>>>(q_coords, support_idxs,
                                           cy_radius, disk_radius, disk_width,
                                           cone_radius, cone_inc, ellip_radii,
                                           lambdas, out, M);
}

// round 17
// speedup vs baseline: 1.1139x; 1.1139x over previous
#include <cuda_runtime.h>
#include <cuda_bf16.h>
#include <cstdint>

// GIB_Layer: M=50000 queries, K=32 support, 4 kinds x G=8 gaussian basis fns,
// masked mean over K, then (32 x 16) mixing matmul. REACH=1, EPS=1e-8.
//
// R17: two-kernel graph, fixing R14's confounds.
//   Kernel 1 (repack): points (N,3) AoS-12B -> static __device__ float4
//     scratch (16B/point), ~1.3 us.
//   Kernel 2 (main): R4/R13 structure (warp per query, grid-stride, hoisted
//     per-lane coefficients + 16-reg lambda slice with 1/K folded in,
//     ballot-compacted exp, pure-shuffle 32x16 epilogue). Gather is ONE
//     aligned LDG.128 per lane via __ldg (forces .nc path — R14 lost it
//     because the compiler can't prove the scratch read-only). Register
//     count pinned via __launch_bounds__(128, 12) (<=42 regs, 48 warps/SM);
//     QPW=7 supplies ~48.3 warps/SM to match.

#define GIB_K     32
#define GIB_OBS   16
#define GIB_F     32          // 4*G features
#define GIB_EPS   1e-8f
#define WPB       4           // warps per block
#define QPW       7           // target queries per warp
#define LOG2E     1.4426950408889634f
#define N_MAX     100000

__device__ float4 g_points4[N_MAX];     // 1.6 MB scratch (static, allowed)

__device__ __forceinline__ float fast_exp2(float x) {
    float y;
    asm("ex2.approx.ftz.f32 %0, %1;" : "=f"(y) : "f"(x));
    return y;
}

__global__ void repack_points_kernel(const float* __restrict__ points, int n)
{
    int i = blockIdx.x * blockDim.x + threadIdx.x;
    if (i < n) {
        g_points4[i] = make_float4(__ldg(points + 3 * i + 0),
                                   __ldg(points + 3 * i + 1),
                                   __ldg(points + 3 * i + 2), 0.f);
    }
}

__global__ __launch_bounds__(WPB * 32, 12)   // pin regs (<=42), 48 warps/SM
void gib_layer_kernel(const float* __restrict__ q_coords,
                      const int*   __restrict__ support_idxs,
                      const float* __restrict__ cy_radius,
                      const float* __restrict__ disk_radius,
                      const float* __restrict__ disk_width,
                      const float* __restrict__ cone_radius,
                      const float* __restrict__ cone_inc,
                      const float* __restrict__ ellip_radii,
                      const float* __restrict__ lambdas,
                      float* __restrict__ out,
                      int M)
{
    const int lane      = threadIdx.x & 31;
    const int warp_glb  = (blockIdx.x * WPB) + (threadIdx.x >> 5);
    const int num_warps = gridDim.x * WPB;

    // ---- per-lane weight coefficients (query-invariant):
    // lane -> (kind = lane>>3, g = lane&7); unified base-2 exponent
    //   a*x2 + b*y2 + c*z2 + d*rz + k0,  rz = sqrt(x2+y2+EPS)*z
    const int kind = lane >> 3;
    const int g    = lane & 7;
    float a, b, c, d, k0;
    {
        const float NHL = -0.5f * LOG2E;
        if (kind == 0) {                  // cylinder
            float r = cy_radius[g];
            float P = NHL / (r * r + GIB_EPS);
            a = P; b = P; c = 0.f; d = 0.f; k0 = 0.f;
        } else if (kind == 1) {           // cone
            float r   = cone_radius[g];
            float inc = cone_inc[g];
            float Q = NHL / (r * r + GIB_EPS);
            a = Q; b = Q; c = Q * inc * inc; d = -2.f * Q * inc; k0 = Q * GIB_EPS;
        } else if (kind == 2) {           // disk
            float dr = disk_radius[g], dw = disk_width[g];
            float Dr = NHL / (dr * dr + GIB_EPS);
            float Dw = NHL / (dw * dw + GIB_EPS);
            a = Dr; b = Dr; c = Dw; d = 0.f; k0 = 0.f;
        } else {                          // ellipsoid
            float ra = ellip_radii[g * 3 + 0];
            float rb = ellip_radii[g * 3 + 1];
            float rc = ellip_radii[g * 3 + 2];
            a = NHL / (ra * ra + GIB_EPS);
            b = NHL / (rb * rb + GIB_EPS);
            c = NHL / (rc * rc + GIB_EPS);
            d = 0.f; k0 = 0.f;
        }
    }

    // ---- per-lane lambda slice (query-invariant), 1/K folded in.
    // lane l handles output o=l&15 over features f=(l&16)+j, j=0..15.
    const int o_idx = lane & 15;
    const int f0    = lane & 16;
    float lam[16];
    #pragma unroll
    for (int j = 0; j < 16; j++)
        lam[j] = lambdas[(f0 + j) * GIB_OBS + o_idx] * (1.0f / (float)GIB_K);

    // ---- query loop (grid-stride): whole warp shares one m per iteration.
    for (int m = warp_glb; m < M; m += num_warps) {
        const int pi = support_idxs[m * GIB_K + lane];
        const float4 v = __ldg(&g_points4[pi]);   // single aligned LDG.128 (.nc)

        const float qx = q_coords[3 * m + 0];
        const float qy = q_coords[3 * m + 1];
        const float qz = q_coords[3 * m + 2];

        const float x = v.x - qx;
        const float y = v.y - qy;
        const float z = v.z - qz;

        const float x2 = x * x, y2 = y * y, z2 = z * z;
        const float d2 = x2 + y2 + z2;
        const float rz = sqrtf(x2 + y2 + GIB_EPS) * z;

        unsigned bal = __ballot_sync(0xffffffffu, d2 <= 1.0f);   // REACH^2=1
        float acc = 0.f;
        while (bal) {
            const int j = __ffs(bal) - 1;
            bal &= bal - 1;
            const float bx2 = __shfl_sync(0xffffffffu, x2, j);
            const float by2 = __shfl_sync(0xffffffffu, y2, j);
            const float bz2 = __shfl_sync(0xffffffffu, z2, j);
            const float brz = __shfl_sync(0xffffffffu, rz, j);
            const float arg = fmaf(a, bx2, fmaf(b, by2, fmaf(c, bz2, fmaf(d, brz, k0))));
            acc += fast_exp2(arg);
        }
        // 1/K folded into lam

        // ---- epilogue: out[m, o] = sum_f feat[f] * lambdas[f, o].
        float oacc = 0.f;
        #pragma unroll
        for (int j = 0; j < 16; j++) {
            const float bf = __shfl_sync(0xffffffffu, acc, f0 | j);
            oacc = fmaf(bf, lam[j], oacc);
        }
        oacc += __shfl_xor_sync(0xffffffffu, oacc, 16);

        if (lane < GIB_OBS)
            out[m * GIB_OBS + lane] = oacc;
    }
}

extern "C" void kernel_launch(void* const* d_in, const int* in_sizes, int n_in,
                              void* d_out, int out_size)
{
    const float* points       = (const float*)d_in[0];
    const float* q_coords     = (const float*)d_in[1];
    const int*   support_idxs = (const int*)  d_in[2];
    const float* cy_radius    = (const float*)d_in[3];
    const float* disk_radius  = (const float*)d_in[4];
    const float* disk_width   = (const float*)d_in[5];
    const float* cone_radius  = (const float*)d_in[6];
    const float* cone_inc     = (const float*)d_in[7];
    const float* ellip_radii  = (const float*)d_in[8];
    const float* lambdas      = (const float*)d_in[9];
    float* out = (float*)d_out;

    int n = in_sizes[0] / 3;              // points is (N, 3)
    if (n > N_MAX) n = N_MAX;
    const int M = in_sizes[1] / 3;        // q_coords is (M, 3)

    repack_points_kernel<<<(n + 255) / 256, 256>>>(points, n);

    int blocks = (M + (WPB * QPW) - 1) / (WPB * QPW);
    if (blocks < 1) blocks = 1;
    gib_layer_kernel<<<blocks, WPB * 32>>>(q_coords, support_idxs,
                                           cy_radius, disk_radius, disk_width,
                                           cone_radius, cone_inc, ellip_radii,
                                           lambdas, out, M);
}